// round 4
// baseline (speedup 1.0000x reference)
#include <cuda_runtime.h>
#include <cuda_bf16.h>
#include <cstdint>

// Problem constants
#define NB   8
#define CC   256
#define HH   50
#define WW   68
#define HW   (HH*WW)           // 3400
#define NR   4000
#define SCALE 0.0625f
#define ROWSTRIDE (WW*CC)      // 17408 floats per y-row in NHWC

// NHWC scratch: 8*3400*256 floats = 27.85 MB (static device global)
__device__ float g_nhwc[NB * HW * CC];

// ---------------------------------------------------------------------------
// Kernel 1: NCHW -> NHWC transpose. 32x32 tiles, 256 threads, 4 elems/thread.
// Loads coalesced along p (spatial); stores as float4 along c (channel).
// ---------------------------------------------------------------------------
__global__ __launch_bounds__(256) void nchw_to_nhwc(const float* __restrict__ in) {
    __shared__ float tile[32][33];
    const int b  = blockIdx.z;
    const int c0 = blockIdx.y * 32;
    const int p0 = blockIdx.x * 32;

    const int tx = threadIdx.x & 31;
    const int ty = threadIdx.x >> 5;
    const int p  = p0 + tx;
    if (p < HW) {
        #pragma unroll
        for (int k = 0; k < 4; k++) {
            int c = c0 + ty + k * 8;
            tile[ty + k * 8][tx] = in[((size_t)b * CC + c) * HW + p];
        }
    }
    __syncthreads();

    const int sp = threadIdx.x >> 3;
    const int cg = threadIdx.x & 7;
    const int pp = p0 + sp;
    if (pp < HW) {
        float4 v;
        v.x = tile[cg * 4 + 0][sp];
        v.y = tile[cg * 4 + 1][sp];
        v.z = tile[cg * 4 + 2][sp];
        v.w = tile[cg * 4 + 3][sp];
        *reinterpret_cast<float4*>(
            &g_nhwc[((size_t)b * HW + pp) * CC + c0 + cg * 4]) = v;
    }
}

// ---------------------------------------------------------------------------
// Kernel 2: RoIAlign. One CTA per roi, one thread per channel.
// Two-phase staging: pooled rows 0-3 (samples 0-4), then rows 4-6 (5-7).
// smem = 256*29 floats = 29.7KB -> target 6 CTAs/SM (reg-limited at 42).
// Only 3 barriers per roi; each preceded by >=3 rows of gathers (deep MLP).
// x-mask packed into bit 0 of xoff (xoff = x0*CC is always even).
// ---------------------------------------------------------------------------
#define SROW 29   // padded per-channel stride (odd -> bank-conflict-free)

__global__ __launch_bounds__(256, 6) void roi_align_kernel(
    const float* __restrict__ rois, float* __restrict__ out)
{
    __shared__ float s_buf[CC * SROW];   // 29696 B

    const int r = blockIdx.x;
    const int c = threadIdx.x;

    const float* roi = rois + r * 5;
    const int   bi = (int)roi[0];
    const float x1 = roi[1] * SCALE;
    const float y1 = roi[2] * SCALE;
    const float x2 = roi[3] * SCALE;
    const float y2 = roi[4] * SCALE;
    const float bin_w = fmaxf(x2 - x1, 0.0f) * (1.0f / 7.0f);
    const float bin_h = fmaxf(y2 - y1, 0.0f) * (1.0f / 7.0f);

    // x-axis geometry: xoff = x0*CC | mask_bit, lxv = fractional x
    int   xoff[8];
    float lxv[8];
    #pragma unroll
    for (int pw = 0; pw < 8; pw++) {
        float w  = x1 + (float)pw * bin_w;
        int   mx = (w >= 0.0f && w < (float)WW) ? 1 : 0;
        float xf = fminf(fmaxf(floorf(w), 0.0f), (float)(WW - 2));
        lxv[pw]  = w - xf;
        xoff[pw] = ((int)xf * CC) | mx;
    }

    const float* fbase = g_nhwc + (size_t)bi * HW * CC + c;
    float* const  obase = out + (size_t)r * (CC * 49);

    float prev[8];

    // ---- sample one row of 8 bilinear taps ----
    #define SAMPLE_ROW(sph, dst)                                              \
    {                                                                         \
        float h  = y1 + (float)(sph) * bin_h;                                 \
        float my = (h >= 0.0f && h < (float)HH) ? 1.0f : 0.0f;                \
        float yf = fminf(fmaxf(floorf(h), 0.0f), (float)(HH - 2));            \
        float ly = h - yf;                                                    \
        const float* r0 = fbase + (int)yf * ROWSTRIDE;                        \
        const float* r1 = r0 + ROWSTRIDE;                                     \
        _Pragma("unroll")                                                     \
        for (int pw = 0; pw < 8; pw++) {                                      \
            int   off = xoff[pw] & ~1;                                        \
            float mm  = my * (float)(xoff[pw] & 1);                           \
            float v00 = __ldg(r0 + off);                                      \
            float v01 = __ldg(r0 + off + CC);                                 \
            float v10 = __ldg(r1 + off);                                      \
            float v11 = __ldg(r1 + off + CC);                                 \
            float top = fmaf(lxv[pw], v01 - v00, v00);                        \
            float bot = fmaf(lxv[pw], v11 - v10, v10);                        \
            dst[pw] = fmaf(ly, bot - top, top) * mm;                          \
        }                                                                     \
    }

    // ================= Phase 0: pooled rows 0..3 (samples 0..4) =============
    SAMPLE_ROW(0, prev);
    #pragma unroll
    for (int sph = 1; sph <= 4; sph++) {
        float s[8];
        SAMPLE_ROW(sph, s);
        const int i = sph - 1;
        #pragma unroll
        for (int pw = 0; pw < 7; pw++) {
            s_buf[c * SROW + i * 7 + pw] =
                0.25f * ((prev[pw] + prev[pw + 1]) + (s[pw] + s[pw + 1]));
        }
        #pragma unroll
        for (int pw = 0; pw < 8; pw++) prev[pw] = s[pw];
    }
    __syncthreads();
    // copy pooled rows 0..3 (28 floats/ch, 7168 total) to global
    #pragma unroll
    for (int k = 0; k < 7; k++) {
        int j   = c + k * CC;          // 0..1791 of 7168
        int ch  = j / 28;
        int rem = j - ch * 28;
        obase[ch * 49 + rem] = s_buf[ch * SROW + rem];
        int j2  = j + 1792;
        int ch2 = j2 / 28;
        int rm2 = j2 - ch2 * 28;
        obase[ch2 * 49 + rm2] = s_buf[ch2 * SROW + rm2];
        int j3  = j + 3584;
        int ch3 = j3 / 28;
        int rm3 = j3 - ch3 * 28;
        obase[ch3 * 49 + rm3] = s_buf[ch3 * SROW + rm3];
        int j4  = j + 5376;
        int ch4 = j4 / 28;
        int rm4 = j4 - ch4 * 28;
        obase[ch4 * 49 + rm4] = s_buf[ch4 * SROW + rm4];
    }
    __syncthreads();   // protect buffer reuse

    // ================= Phase 1: pooled rows 4..6 (samples 5..7, prev=row4) ==
    #pragma unroll
    for (int sph = 5; sph <= 7; sph++) {
        float s[8];
        SAMPLE_ROW(sph, s);
        const int i = sph - 5;          // 0..2 -> pooled rows 4..6
        #pragma unroll
        for (int pw = 0; pw < 7; pw++) {
            s_buf[c * SROW + i * 7 + pw] =
                0.25f * ((prev[pw] + prev[pw + 1]) + (s[pw] + s[pw + 1]));
        }
        #pragma unroll
        for (int pw = 0; pw < 8; pw++) prev[pw] = s[pw];
    }
    __syncthreads();
    // copy pooled rows 4..6 (21 floats/ch, 5376 total) to global
    #pragma unroll
    for (int k = 0; k < 7; k++) {
        int j   = c + k * CC;          // 0..1791
        int ch  = j / 21;
        int rem = j - ch * 21;
        obase[ch * 49 + 28 + rem] = s_buf[ch * SROW + rem];
        int j2  = j + 1792;
        int ch2 = j2 / 21;
        int rm2 = j2 - ch2 * 21;
        obase[ch2 * 49 + 28 + rm2] = s_buf[ch2 * SROW + rm2];
        int j3  = j + 3584;
        if (j3 < 5376) {
            int ch3 = j3 / 21;
            int rm3 = j3 - ch3 * 21;
            obase[ch3 * 49 + 28 + rm3] = s_buf[ch3 * SROW + rm3];
        }
    }
    #undef SAMPLE_ROW
}

// ---------------------------------------------------------------------------
extern "C" void kernel_launch(void* const* d_in, const int* in_sizes, int n_in,
                              void* d_out, int out_size)
{
    const float* features = (const float*)d_in[0];  // [8,256,50,68]
    const float* rois     = (const float*)d_in[1];  // [4000,5]
    float*       out      = (float*)d_out;          // [4000,256,7,7]

    dim3 tg((HW + 31) / 32, CC / 32, NB);
    nchw_to_nhwc<<<tg, 256>>>(features);

    roi_align_kernel<<<NR, CC>>>(rois, out);
}